// round 8
// baseline (speedup 1.0000x reference)
#include <cuda_runtime.h>
#include <cuda_bf16.h>
#include <math.h>
#include <stdint.h>

// ---------------- problem constants ----------------
#define D_H 256
#define D_S 552
#define LT  128
#define NB_ 64
#define MAXDEC 1000
#define G4 1024
#define M_ENC (LT*NB_)       // 8192
#define M_DEC (MAXDEC*NB_)   // 64000
#define M_VAL 51200          // rows with non-trivial S_in
#define STOP_OFF ((size_t)M_DEC * D_S)
#define KP_S 560
#define NSEG 4
#define SEG_STEPS 250
#define SEG_ROWS  (SEG_STEPS*NB_)   // 16000

// ---------------- device scratch ----------------
__device__ __align__(256) float g_TE[M_ENC * D_H];
__device__ __align__(256) float g_XencG[M_ENC * G4];
__device__ __align__(256) float g_Xd[(size_t)M_VAL * D_H];
__device__ __align__(256) float g_XdG[(size_t)M_VAL * G4];
__device__ __align__(256) float g_H[(size_t)M_DEC * D_H];
__device__ __align__(256) float g_Hid[(size_t)M_DEC * D_H];
__device__ __align__(256) float g_StopP[M_DEC];
__device__ __align__(256) float g_Wr[995328];
__device__ __align__(256) float g_bcat[512];
__device__ __align__(256) float g_cvec[G4];
__device__ float g_hbuf[2 * D_H * NB_];
__device__ float g_cbuf[D_H * NB_];
__device__ unsigned int g_bar;

#define W_ENC   0
#define W_DEC   262144
#define W_PRE   524288
#define W_P1S   667648
#define W_POST2 798720

__device__ __forceinline__ float to_tf32(float x) {
    float r; asm("cvt.rna.tf32.f32 %0, %1;" : "=f"(r) : "f"(x)); return r;
}

// ---------------- fused prep ----------------
#define P_HB  32768
#define P_BC  (P_HB + 512)
#define P_ENC (P_BC + 262144)
#define P_DEC (P_ENC + 262144)
#define P_PRE (P_DEC + 143360)
#define P_W1  (P_PRE + 65536)
#define P_S1  (P_W1 + 65536)
#define P_W2  (P_S1 + 196608)

__global__ void prep_k(const float* __restrict__ encWih, const float* __restrict__ decWih,
                       const float* __restrict__ preW,  const float* __restrict__ postW1,
                       const float* __restrict__ stopW1,const float* __restrict__ postW2,
                       const float* __restrict__ b1,    const float* __restrict__ b2) {
    int idx = blockIdx.x * 256 + threadIdx.x;
    if (idx == 0) g_bar = 0u;
    if (idx < P_HB) { g_hbuf[idx] = 0.f; return; }
    if (idx < P_BC) { int i = idx - P_HB; g_bcat[i] = (i < 256) ? b1[i] : b2[i - 256]; return; }
    if (idx < P_ENC){ int i = idx - P_BC; g_Wr[W_ENC + i] = to_tf32(encWih[i]); return; }
    if (idx < P_DEC){ int i = idx - P_ENC; g_Wr[W_DEC + i] = to_tf32(decWih[i]); return; }
    if (idx < P_PRE){ int i = idx - P_DEC; int r = i / KP_S, c = i - r * KP_S;
                      g_Wr[W_PRE + i] = (c < D_S) ? to_tf32(preW[r * D_S + c]) : 0.f; return; }
    if (idx < P_W1) { int i = idx - P_PRE; g_Wr[W_P1S + i] = to_tf32(postW1[i]); return; }
    if (idx < P_S1) { int i = idx - P_W1;  g_Wr[W_P1S + 65536 + i] = to_tf32(stopW1[i]); return; }
    if (idx < P_W2) { int i = idx - P_S1;  int r = i >> 8;
                      g_Wr[W_POST2 + i] = (r < D_S) ? to_tf32(postW2[i]) : 0.f; return; }
}

__global__ void gather_emb(const int* __restrict__ tok, const float* __restrict__ emb,
                           float* __restrict__ te) {
    int r = blockIdx.x;
    int k = threadIdx.x;
    te[r * D_H + k] = to_tf32(emb[tok[r] * D_H + k]);
}

__global__ void cvec_k(const float* __restrict__ pre_b,
                       const float* __restrict__ bih, const float* __restrict__ bhh) {
    int n = blockIdx.x * 8 + (threadIdx.x >> 5);
    int lane = threadIdx.x & 31;
    float acc = 0.f;
#pragma unroll
    for (int k = lane; k < 256; k += 32)
        acc += to_tf32(pre_b[k]) * g_Wr[W_DEC + n * 256 + k];
#pragma unroll
    for (int o = 16; o; o >>= 1) acc += __shfl_down_sync(0xffffffffu, acc, o);
    if (lane == 0) g_cvec[n] = acc + bih[n] + bhh[n];
}

// ---------------- tf32 tensor-core GEMM (unchanged from R7) ----------------
#define BM 128
#define BN 256
#define BK 16
#define SL 20
#define ST_AGES 3
#define AOFF(s) ((s) * (BM * SL))
#define BOFF(s) (ST_AGES * BM * SL + (s) * (BN * SL))
#define GEMM_SMEM (ST_AGES * (BM + BN) * SL * 4)

__device__ __forceinline__ void cp16(uint32_t s, const void* g) {
    asm volatile("cp.async.cg.shared.global [%0], [%1], 16;" :: "r"(s), "l"(g));
}

template<int RA>
__global__ void __launch_bounds__(256, 1) gemm_tc(
    const float* __restrict__ A, int lda, int rowlo, int rowhi, int kvalid,
    const float* __restrict__ B, int ldb,
    const float* __restrict__ bias0, const float* __restrict__ bias1,
    float* __restrict__ C, int M, int N, int K,
    int cmode, int dorelu, int doround,
    const float* __restrict__ w2, float* __restrict__ stopP)
{
    extern __shared__ float smp[];
    __shared__ float spart[4][BM];

    const int tid  = threadIdx.x;
    const int bm   = blockIdx.x * BM;
    const int bn   = blockIdx.y * BN;
    const int warp = tid >> 5, lane = tid & 31;
    const int wm   = (warp & 1) * 64;
    const int wn   = (warp >> 1) * 64;
    const int grp  = lane >> 2;
    const int tig  = lane & 3;

    float acc[4][8][4];
#pragma unroll
    for (int i = 0; i < 4; i++)
#pragma unroll
        for (int j = 0; j < 8; j++)
#pragma unroll
            for (int e = 0; e < 4; e++) acc[i][j][e] = 0.f;

    const int T = K / BK;

#define LOAD_TILE(t)                                                            \
    {                                                                           \
        int k0 = (t) * BK;                                                      \
        int sb = (t) % ST_AGES;                                                 \
        _Pragma("unroll")                                                       \
        for (int i = 0; i < 2; i++) {                                           \
            int f = i * 256 + tid, row = f >> 2, seg = (f & 3) * 4;             \
            int ar = bm + row, kk = k0 + seg;                                   \
            float* da = smp + AOFF(sb) + row * SL + seg;                        \
            if (ar >= rowlo && ar < rowhi && kk < kvalid)                       \
                cp16((uint32_t)__cvta_generic_to_shared(da),                    \
                     A + (size_t)ar * lda + kk);                                \
            else                                                                \
                *(float4*)da = make_float4(0.f, 0.f, 0.f, 0.f);                 \
        }                                                                       \
        _Pragma("unroll")                                                       \
        for (int i = 0; i < 4; i++) {                                           \
            int f = i * 256 + tid, row = f >> 2, seg = (f & 3) * 4;             \
            float* db = smp + BOFF(sb) + row * SL + seg;                        \
            cp16((uint32_t)__cvta_generic_to_shared(db),                        \
                 B + (size_t)(bn + row) * ldb + k0 + seg);                      \
        }                                                                       \
        asm volatile("cp.async.commit_group;" ::: "memory");                    \
    }

    LOAD_TILE(0);
    LOAD_TILE(1);

    for (int t = 0; t < T; t++) {
        asm volatile("cp.async.wait_group 1;" ::: "memory");
        __syncthreads();
        if (t + 2 < T) LOAD_TILE(t + 2);

        const uint32_t* as = reinterpret_cast<const uint32_t*>(smp + AOFF(t % ST_AGES));
        const uint32_t* bs = reinterpret_cast<const uint32_t*>(smp + BOFF(t % ST_AGES));

#pragma unroll
        for (int kk = 0; kk < BK; kk += 8) {
            uint32_t a[4][4], b[8][2];
            const int c0 = kk + tig;
#pragma unroll
            for (int mt = 0; mt < 4; mt++) {
                int r0 = wm + mt * 16 + grp;
                a[mt][0] = as[r0 * SL + c0];
                a[mt][1] = as[(r0 + 8) * SL + c0];
                a[mt][2] = as[r0 * SL + c0 + 4];
                a[mt][3] = as[(r0 + 8) * SL + c0 + 4];
                if (RA) {
#pragma unroll
                    for (int q = 0; q < 4; q++)
                        a[mt][q] = __float_as_uint(to_tf32(__uint_as_float(a[mt][q])));
                }
            }
#pragma unroll
            for (int nt = 0; nt < 8; nt++) {
                int n0 = wn + nt * 8 + grp;
                b[nt][0] = bs[n0 * SL + c0];
                b[nt][1] = bs[n0 * SL + c0 + 4];
            }
#pragma unroll
            for (int mt = 0; mt < 4; mt++)
#pragma unroll
                for (int nt = 0; nt < 8; nt++) {
                    asm volatile(
                        "mma.sync.aligned.m16n8k8.row.col.f32.tf32.tf32.f32 "
                        "{%0,%1,%2,%3}, {%4,%5,%6,%7}, {%8,%9}, {%0,%1,%2,%3};"
                        : "+f"(acc[mt][nt][0]), "+f"(acc[mt][nt][1]),
                          "+f"(acc[mt][nt][2]), "+f"(acc[mt][nt][3])
                        : "r"(a[mt][0]), "r"(a[mt][1]), "r"(a[mt][2]), "r"(a[mt][3]),
                          "r"(b[nt][0]), "r"(b[nt][1]));
                }
        }
        __syncthreads();
    }
#undef LOAD_TILE

    if (cmode == 2 && bn == 256) {
        float myp[4][2];
#pragma unroll
        for (int mt = 0; mt < 4; mt++) { myp[mt][0] = 0.f; myp[mt][1] = 0.f; }
#pragma unroll
        for (int nt = 0; nt < 8; nt++)
#pragma unroll
            for (int e = 0; e < 4; e++) {
                int col = bn + wn + nt * 8 + tig * 2 + (e & 1);
                float wv = __ldg(w2 + (col - 256));
                float bv = __ldg(bias0 + col);
#pragma unroll
                for (int mt = 0; mt < 4; mt++) {
                    float v = fmaxf(acc[mt][nt][e] + bv, 0.f);
                    myp[mt][e >> 1] += v * wv;
                }
            }
#pragma unroll
        for (int mt = 0; mt < 4; mt++)
#pragma unroll
            for (int h = 0; h < 2; h++) {
                float v = myp[mt][h];
                v += __shfl_xor_sync(0xffffffffu, v, 1);
                v += __shfl_xor_sync(0xffffffffu, v, 2);
                myp[mt][h] = v;
            }
        if (tig == 0) {
            int wi = warp >> 1;
#pragma unroll
            for (int mt = 0; mt < 4; mt++)
#pragma unroll
                for (int h = 0; h < 2; h++)
                    spart[wi][wm + mt * 16 + grp + 8 * h] = myp[mt][h];
        }
        __syncthreads();
        if (tid < BM)
            stopP[bm + tid] = spart[0][tid] + spart[1][tid] + spart[2][tid] + spart[3][tid];
        return;
    }

#pragma unroll
    for (int nt = 0; nt < 8; nt++) {
#pragma unroll
        for (int e = 0; e < 4; e++) {
            int col = bn + wn + nt * 8 + tig * 2 + (e & 1);
            if (col >= N) continue;
            float bv = 0.f;
            if (bias0) bv += __ldg(bias0 + col);
            if (bias1) bv += __ldg(bias1 + col);
#pragma unroll
            for (int mt = 0; mt < 4; mt++) {
                int row = bm + wm + mt * 16 + grp + ((e >> 1) << 3);
                float v = acc[mt][nt][e] + bv;
                if (dorelu) v = fmaxf(v, 0.f);
                if (doround) v = to_tf32(v);
                if (cmode == 0)
                    C[(size_t)row * N + col] = v;
                else if (cmode == 1)
                    C[(size_t)(row >> 6) * (64 * (size_t)N) + (size_t)col * 64 + (row & 63)] = v;
                else
                    C[(size_t)row * 256 + col] = v;
            }
        }
    }
}

// ---------------- stop finalize ----------------
__global__ void stopfin_k(const float* __restrict__ b2, float* __restrict__ out) {
    int r = blockIdx.x * 256 + threadIdx.x;
    if (r < M_DEC) out[r] = g_StopP[r] + b2[0];
}

// ---------------- recurrent LSTM: 2-D partition (32 col-groups x 4 batch-groups) ----------------
__device__ __forceinline__ float sigmoidf_(float x) { return 1.f / (1.f + __expf(-x)); }

__device__ __forceinline__ void bar_wait(int tid, unsigned int tgt) {
    if (tid == 0) {
        unsigned int v;
        do { asm volatile("ld.acquire.gpu.u32 %0, [%1];" : "=r"(v) : "l"(&g_bar)); }
        while (v < tgt);
    }
    __syncthreads();
}
__device__ __forceinline__ void bar_arrive(int tid) {
    __syncthreads();
    if (tid == 0)
        asm volatile("red.release.gpu.add.u32 [%0], %1;" :: "l"(&g_bar), "r"(1u) : "memory");
}

#define SEQ_NB 128
#define SEQ_NT 256
#define WPAD 258
// dynamic smem: float2 Ws2[32][WPAD]  +  float part[8][32][16]
#define LSTM_SMEM ((2 * 32 * WPAD + 8 * 32 * 16) * 4)

// DEC=0: encoder steps [0,LT), uses g_XencG + length mask
// DEC=1: decoder steps [s0,s1e), uses g_XdG / g_cvec, writes g_H, c spill to g_cbuf
template<int DEC>
__global__ void __launch_bounds__(SEQ_NT, 1) lstm_k(
    const float* __restrict__ Whh, const int* __restrict__ tlen, int s0, int s1e)
{
    extern __shared__ float sm[];
    float2* Ws2  = (float2*)sm;             // [32][WPAD]
    float*  part = sm + 2 * 32 * WPAD;      // [8][32][16]

    const int tid  = threadIdx.x;
    const int blk  = blockIdx.x;
    const int cg   = blk >> 2;              // 0..31
    const int bg   = blk & 3;               // 0..3
    const int j0   = cg * 8;                // 8 h-cols
    const int b0   = bg * 16;               // 16 batches
    const int warp = tid >> 5, lane = tid & 31;
    const int rg   = lane >> 2;             // 0..7 -> rows rg*4..rg*4+4
    const int bpg  = lane & 3;              // 0..3 -> batch quad b0+bpg*4
    const int kbeg = warp * 32;

    // load weights duplicated-pair, padded stride (no bank conflicts)
    for (int idx = tid; idx < 32 * 256; idx += SEQ_NT) {
        int gl = idx >> 8, k = idx & 255;
        int g = gl >> 3, jj = gl & 7;
        float w = Whh[(g * 256 + j0 + jj) * 256 + k];
        Ws2[gl * WPAD + k] = make_float2(w, w);
    }

    // update mapping: thread t<128 owns output (col j0+ujj, batch b0+ubb)
    const int ujj = tid >> 4, ubb = tid & 15;
    const int uj = j0 + ujj, ub = b0 + ubb;
    const bool upd = (tid < 128);
    float c_reg = 0.f;
    const int mylen = (DEC == 0 && upd) ? tlen[ub] : 0;
    if (DEC == 1 && upd && s0 > LT) c_reg = g_cbuf[uj * 64 + ub];
    __syncthreads();

    for (int s = s0; s < s1e; s++) {
        bar_wait(tid, (unsigned int)(SEQ_NB * s));

        const int cur = s & 1, nxt = cur ^ 1;
        const float* hb = g_hbuf + cur * (D_H * NB_);

        // prefetch x-part gate values
        float gvx[4];
        if (upd) {
            if (DEC == 1) {
                int t = s - LT;
                if (t < 800) {
#pragma unroll
                    for (int g = 0; g < 4; g++)
                        gvx[g] = __ldcg(g_XdG + (size_t)t * ((size_t)G4 * NB_)
                                        + ((g * 256 + uj) << 6) + ub);
                } else {
#pragma unroll
                    for (int g = 0; g < 4; g++)
                        gvx[g] = __ldg(g_cvec + g * 256 + uj);
                }
            } else {
#pragma unroll
                for (int g = 0; g < 4; g++)
                    gvx[g] = __ldcg(g_XencG + (size_t)s * (G4 * NB_)
                                    + ((g * 256 + uj) << 6) + ub);
            }
        }

        // partial gate GEMM over this warp's k-slice: 4 rows x 4 batches per lane
        unsigned long long acc[4][2];
#pragma unroll
        for (int i = 0; i < 4; i++) { acc[i][0] = 0ull; acc[i][1] = 0ull; }
#pragma unroll 8
        for (int k = kbeg; k < kbeg + 32; k++) {
            ulonglong2 hq = __ldcg((const ulonglong2*)(hb + k * 64 + b0 + bpg * 4));
#pragma unroll
            for (int i = 0; i < 4; i++) {
                unsigned long long w = *(const unsigned long long*)&Ws2[(rg * 4 + i) * WPAD + k];
                asm("fma.rn.f32x2 %0, %1, %2, %0;" : "+l"(acc[i][0]) : "l"(hq.x), "l"(w));
                asm("fma.rn.f32x2 %0, %1, %2, %0;" : "+l"(acc[i][1]) : "l"(hq.y), "l"(w));
            }
        }
#pragma unroll
        for (int i = 0; i < 4; i++) {
            *(float2*)&part[(warp * 32 + rg * 4 + i) * 16 + bpg * 4 + 0] = *(float2*)&acc[i][0];
            *(float2*)&part[(warp * 32 + rg * 4 + i) * 16 + bpg * 4 + 2] = *(float2*)&acc[i][1];
        }
        __syncthreads();

        if (upd) {
            float gv[4];
#pragma unroll
            for (int g = 0; g < 4; g++) {
                int gl = g * 8 + ujj;
                float v = gvx[g];
#pragma unroll
                for (int w = 0; w < 8; w++) v += part[(w * 32 + gl) * 16 + ubb];
                gv[g] = v;
            }
            if (DEC == 1 && s == LT)
                c_reg = __ldcg(hb + uj * 64 + ub);

            float iv = sigmoidf_(gv[0]);
            float fv = sigmoidf_(gv[1]);
            float gg = tanhf(gv[2]);
            float ov = sigmoidf_(gv[3]);
            float c2 = fv * c_reg + iv * gg;
            float h2 = ov * tanhf(c2);
            float hnew;
            if (DEC == 0) {
                bool m = (s < mylen);
                float hold = __ldcg(hb + uj * 64 + ub);
                c_reg = m ? c2 : c_reg;
                hnew  = m ? h2 : hold;
            } else {
                c_reg = c2;
                hnew  = h2;
                g_H[(size_t)(s - LT) * (NB_ * D_H) + ub * D_H + uj] = to_tf32(h2);
            }
            g_hbuf[nxt * (D_H * NB_) + uj * 64 + ub] = hnew;
        }
        bar_arrive(tid);
    }
    if (DEC == 1 && upd) g_cbuf[uj * 64 + ub] = c_reg;
}

// ---------------- launch ----------------
extern "C" void kernel_launch(void* const* d_in, const int* in_sizes, int n_in,
                              void* d_out, int out_size) {
    const int*   token_pad     = (const int*)  d_in[0];
    const int*   token_lengths = (const int*)  d_in[1];
    const float* S_true        = (const float*)d_in[2];
    const float* emb           = (const float*)d_in[3];
    const float* enc_Wih       = (const float*)d_in[4];
    const float* enc_Whh       = (const float*)d_in[5];
    const float* enc_bih       = (const float*)d_in[6];
    const float* enc_bhh       = (const float*)d_in[7];
    const float* dec_Wih       = (const float*)d_in[8];
    const float* dec_Whh       = (const float*)d_in[9];
    const float* dec_bih       = (const float*)d_in[10];
    const float* dec_bhh       = (const float*)d_in[11];
    const float* pre_W         = (const float*)d_in[12];
    const float* pre_b         = (const float*)d_in[13];
    const float* post_W1       = (const float*)d_in[14];
    const float* post_b1       = (const float*)d_in[15];
    const float* post_W2       = (const float*)d_in[16];
    const float* post_b2       = (const float*)d_in[17];
    const float* stop_W1       = (const float*)d_in[18];
    const float* stop_b1       = (const float*)d_in[19];
    const float* stop_W2       = (const float*)d_in[20];
    const float* stop_b2       = (const float*)d_in[21];
    float* out = (float*)d_out;

    float *pTE, *pXencG, *pXd, *pXdG, *pH, *pHid, *pWr, *pStopP, *pBcat;
    cudaGetSymbolAddress((void**)&pTE,    g_TE);
    cudaGetSymbolAddress((void**)&pXencG, g_XencG);
    cudaGetSymbolAddress((void**)&pXd,    g_Xd);
    cudaGetSymbolAddress((void**)&pXdG,   g_XdG);
    cudaGetSymbolAddress((void**)&pH,     g_H);
    cudaGetSymbolAddress((void**)&pHid,   g_Hid);
    cudaGetSymbolAddress((void**)&pWr,    g_Wr);
    cudaGetSymbolAddress((void**)&pStopP, g_StopP);
    cudaGetSymbolAddress((void**)&pBcat,  g_bcat);

    static bool s_init = false;
    static cudaStream_t s1, s2;
    static cudaEvent_t evR, evD, evJ, evL[NSEG];
    if (!s_init) {
        s_init = true;
        cudaStreamCreateWithFlags(&s1, cudaStreamNonBlocking);
        cudaStreamCreateWithFlags(&s2, cudaStreamNonBlocking);
        cudaEventCreateWithFlags(&evR, cudaEventDisableTiming);
        cudaEventCreateWithFlags(&evD, cudaEventDisableTiming);
        cudaEventCreateWithFlags(&evJ, cudaEventDisableTiming);
        for (int i = 0; i < NSEG; i++) cudaEventCreateWithFlags(&evL[i], cudaEventDisableTiming);
        cudaFuncSetAttribute(gemm_tc<0>, cudaFuncAttributeMaxDynamicSharedMemorySize, GEMM_SMEM);
        cudaFuncSetAttribute(gemm_tc<1>, cudaFuncAttributeMaxDynamicSharedMemorySize, GEMM_SMEM);
        cudaFuncSetAttribute(lstm_k<0>,  cudaFuncAttributeMaxDynamicSharedMemorySize, LSTM_SMEM);
        cudaFuncSetAttribute(lstm_k<1>,  cudaFuncAttributeMaxDynamicSharedMemorySize, LSTM_SMEM);
    }

    // ---- stream 0: prep ----
    prep_k<<<(P_W2 + 255) / 256, 256>>>(enc_Wih, dec_Wih, pre_W, post_W1, stop_W1, post_W2,
                                        post_b1, stop_b1);
    gather_emb<<<M_ENC, 256>>>(token_pad, emb, pTE);
    cudaEventRecord(evR, 0);
    gemm_tc<0><<<dim3(M_ENC/128, G4/256), 256, GEMM_SMEM>>>(pTE, 256, 0, M_ENC, 256,
        pWr + W_ENC, 256, enc_bih, enc_bhh, pXencG, M_ENC, G4, 256, 1, 0, 0, nullptr, nullptr);
    lstm_k<0><<<SEQ_NB, SEQ_NT, LSTM_SMEM>>>(enc_Whh, token_lengths, 0, LT);

    // ---- s1: pre-net + dec-gate + cvec, overlapping the encoder ----
    cudaStreamWaitEvent(s1, evR, 0);
    gemm_tc<1><<<dim3(M_VAL/128, 1), 256, GEMM_SMEM, s1>>>(S_true, D_S, 64, M_VAL, D_S,
        pWr + W_PRE, KP_S, pre_b, nullptr, pXd, M_VAL, D_H, KP_S, 0, 0, 1, nullptr, nullptr);
    gemm_tc<0><<<dim3(M_VAL/128, G4/256), 256, GEMM_SMEM, s1>>>(pXd, 256, 0, M_VAL, 256,
        pWr + W_DEC, 256, dec_bih, dec_bhh, pXdG, M_VAL, G4, 256, 1, 0, 0, nullptr, nullptr);
    cvec_k<<<G4/8, 256, 0, s1>>>(pre_b, dec_bih, dec_bhh);
    cudaEventRecord(evD, s1);

    // ---- stream 0: decoder recurrence in segments ----
    cudaStreamWaitEvent(0, evD, 0);
    for (int i = 0; i < NSEG; i++) {
        lstm_k<1><<<SEQ_NB, SEQ_NT, LSTM_SMEM>>>(dec_Whh, token_lengths,
                                                 LT + i * SEG_STEPS, LT + (i + 1) * SEG_STEPS);
        cudaEventRecord(evL[i], 0);
    }

    // ---- s2: per-segment post-net chunks overlap the decoder recurrence ----
    for (int i = 0; i < NSEG; i++) {
        cudaStreamWaitEvent(s2, evL[i], 0);
        const float* Hc  = pH   + (size_t)SEG_ROWS * i * 256;
        float*       Hic = pHid + (size_t)SEG_ROWS * i * 256;
        gemm_tc<0><<<dim3(SEG_ROWS/128, 2), 256, GEMM_SMEM, s2>>>(Hc, 256, 0, SEG_ROWS, 256,
            pWr + W_P1S, 256, pBcat, nullptr, Hic, SEG_ROWS, 512, 256, 2, 1, 1,
            stop_W2, pStopP + (size_t)SEG_ROWS * i);
        gemm_tc<0><<<dim3(SEG_ROWS/128, 3), 256, GEMM_SMEM, s2>>>(Hic, 256, 0, SEG_ROWS, 256,
            pWr + W_POST2, 256, post_b2, nullptr, out + (size_t)SEG_ROWS * i * D_S,
            SEG_ROWS, D_S, 256, 0, 0, 0, nullptr, nullptr);
    }
    stopfin_k<<<(M_DEC+255)/256, 256, 0, s2>>>(stop_b2, out + STOP_OFF);
    cudaEventRecord(evJ, s2);

    cudaStreamWaitEvent(0, evJ, 0);
}

// round 9
// speedup vs baseline: 1.0201x; 1.0201x over previous
#include <cuda_runtime.h>
#include <cuda_bf16.h>
#include <math.h>
#include <stdint.h>

// ---------------- problem constants ----------------
#define D_H 256
#define D_S 552
#define LT  128
#define NB_ 64
#define MAXDEC 1000
#define G4 1024
#define M_ENC (LT*NB_)       // 8192
#define M_DEC (MAXDEC*NB_)   // 64000
#define M_VAL 51200          // rows with non-trivial S_in
#define STOP_OFF ((size_t)M_DEC * D_S)
#define KP_S 560
#define NSEG 4
#define SEG_STEPS 250
#define SEG_ROWS  (SEG_STEPS*NB_)   // 16000

// ---------------- device scratch ----------------
__device__ __align__(256) float g_TE[M_ENC * D_H];
__device__ __align__(256) float g_XencG[M_ENC * G4];
__device__ __align__(256) float g_Xd[(size_t)M_VAL * D_H];
__device__ __align__(256) float g_XdG[(size_t)M_VAL * G4];
__device__ __align__(256) float g_H[(size_t)M_DEC * D_H];
__device__ __align__(256) float g_Hid[(size_t)M_DEC * D_H];
__device__ __align__(256) float g_StopP[M_DEC];
__device__ __align__(256) float g_Wr[995328];
__device__ __align__(256) float g_bcat[512];
__device__ __align__(256) float g_cvec[G4];
__device__ float g_hbuf[2 * D_H * NB_];
__device__ float g_cbuf[D_H * NB_];
__device__ __align__(256) unsigned int g_bar4[128];   // 4 chain counters, 128B apart

#define W_ENC   0
#define W_DEC   262144
#define W_PRE   524288
#define W_P1S   667648
#define W_POST2 798720

__device__ __forceinline__ float to_tf32(float x) {
    float r; asm("cvt.rna.tf32.f32 %0, %1;" : "=f"(r) : "f"(x)); return r;
}

// ---------------- fused prep ----------------
#define P_HB  32768
#define P_BC  (P_HB + 512)
#define P_ENC (P_BC + 262144)
#define P_DEC (P_ENC + 262144)
#define P_PRE (P_DEC + 143360)
#define P_W1  (P_PRE + 65536)
#define P_S1  (P_W1 + 65536)
#define P_W2  (P_S1 + 196608)

__global__ void prep_k(const float* __restrict__ encWih, const float* __restrict__ decWih,
                       const float* __restrict__ preW,  const float* __restrict__ postW1,
                       const float* __restrict__ stopW1,const float* __restrict__ postW2,
                       const float* __restrict__ b1,    const float* __restrict__ b2) {
    int idx = blockIdx.x * 256 + threadIdx.x;
    if (idx < 128) g_bar4[idx] = 0u;
    if (idx < P_HB) { g_hbuf[idx] = 0.f; return; }
    if (idx < P_BC) { int i = idx - P_HB; g_bcat[i] = (i < 256) ? b1[i] : b2[i - 256]; return; }
    if (idx < P_ENC){ int i = idx - P_BC; g_Wr[W_ENC + i] = to_tf32(encWih[i]); return; }
    if (idx < P_DEC){ int i = idx - P_ENC; g_Wr[W_DEC + i] = to_tf32(decWih[i]); return; }
    if (idx < P_PRE){ int i = idx - P_DEC; int r = i / KP_S, c = i - r * KP_S;
                      g_Wr[W_PRE + i] = (c < D_S) ? to_tf32(preW[r * D_S + c]) : 0.f; return; }
    if (idx < P_W1) { int i = idx - P_PRE; g_Wr[W_P1S + i] = to_tf32(postW1[i]); return; }
    if (idx < P_S1) { int i = idx - P_W1;  g_Wr[W_P1S + 65536 + i] = to_tf32(stopW1[i]); return; }
    if (idx < P_W2) { int i = idx - P_S1;  int r = i >> 8;
                      g_Wr[W_POST2 + i] = (r < D_S) ? to_tf32(postW2[i]) : 0.f; return; }
}

__global__ void gather_emb(const int* __restrict__ tok, const float* __restrict__ emb,
                           float* __restrict__ te) {
    int r = blockIdx.x;
    int k = threadIdx.x;
    te[r * D_H + k] = to_tf32(emb[tok[r] * D_H + k]);
}

__global__ void cvec_k(const float* __restrict__ pre_b,
                       const float* __restrict__ bih, const float* __restrict__ bhh) {
    int n = blockIdx.x * 8 + (threadIdx.x >> 5);
    int lane = threadIdx.x & 31;
    float acc = 0.f;
#pragma unroll
    for (int k = lane; k < 256; k += 32)
        acc += to_tf32(pre_b[k]) * g_Wr[W_DEC + n * 256 + k];
#pragma unroll
    for (int o = 16; o; o >>= 1) acc += __shfl_down_sync(0xffffffffu, acc, o);
    if (lane == 0) g_cvec[n] = acc + bih[n] + bhh[n];
}

// ---------------- tf32 tensor-core GEMM (unchanged) ----------------
#define BM 128
#define BN 256
#define BK 16
#define SL 20
#define ST_AGES 3
#define AOFF(s) ((s) * (BM * SL))
#define BOFF(s) (ST_AGES * BM * SL + (s) * (BN * SL))
#define GEMM_SMEM (ST_AGES * (BM + BN) * SL * 4)

__device__ __forceinline__ void cp16(uint32_t s, const void* g) {
    asm volatile("cp.async.cg.shared.global [%0], [%1], 16;" :: "r"(s), "l"(g));
}

template<int RA>
__global__ void __launch_bounds__(256, 1) gemm_tc(
    const float* __restrict__ A, int lda, int rowlo, int rowhi, int kvalid,
    const float* __restrict__ B, int ldb,
    const float* __restrict__ bias0, const float* __restrict__ bias1,
    float* __restrict__ C, int M, int N, int K,
    int cmode, int dorelu, int doround,
    const float* __restrict__ w2, float* __restrict__ stopP)
{
    extern __shared__ float smp[];
    __shared__ float spart[4][BM];

    const int tid  = threadIdx.x;
    const int bm   = blockIdx.x * BM;
    const int bn   = blockIdx.y * BN;
    const int warp = tid >> 5, lane = tid & 31;
    const int wm   = (warp & 1) * 64;
    const int wn   = (warp >> 1) * 64;
    const int grp  = lane >> 2;
    const int tig  = lane & 3;

    float acc[4][8][4];
#pragma unroll
    for (int i = 0; i < 4; i++)
#pragma unroll
        for (int j = 0; j < 8; j++)
#pragma unroll
            for (int e = 0; e < 4; e++) acc[i][j][e] = 0.f;

    const int T = K / BK;

#define LOAD_TILE(t)                                                            \
    {                                                                           \
        int k0 = (t) * BK;                                                      \
        int sb = (t) % ST_AGES;                                                 \
        _Pragma("unroll")                                                       \
        for (int i = 0; i < 2; i++) {                                           \
            int f = i * 256 + tid, row = f >> 2, seg = (f & 3) * 4;             \
            int ar = bm + row, kk = k0 + seg;                                   \
            float* da = smp + AOFF(sb) + row * SL + seg;                        \
            if (ar >= rowlo && ar < rowhi && kk < kvalid)                       \
                cp16((uint32_t)__cvta_generic_to_shared(da),                    \
                     A + (size_t)ar * lda + kk);                                \
            else                                                                \
                *(float4*)da = make_float4(0.f, 0.f, 0.f, 0.f);                 \
        }                                                                       \
        _Pragma("unroll")                                                       \
        for (int i = 0; i < 4; i++) {                                           \
            int f = i * 256 + tid, row = f >> 2, seg = (f & 3) * 4;             \
            float* db = smp + BOFF(sb) + row * SL + seg;                        \
            cp16((uint32_t)__cvta_generic_to_shared(db),                        \
                 B + (size_t)(bn + row) * ldb + k0 + seg);                      \
        }                                                                       \
        asm volatile("cp.async.commit_group;" ::: "memory");                    \
    }

    LOAD_TILE(0);
    LOAD_TILE(1);

    for (int t = 0; t < T; t++) {
        asm volatile("cp.async.wait_group 1;" ::: "memory");
        __syncthreads();
        if (t + 2 < T) LOAD_TILE(t + 2);

        const uint32_t* as = reinterpret_cast<const uint32_t*>(smp + AOFF(t % ST_AGES));
        const uint32_t* bs = reinterpret_cast<const uint32_t*>(smp + BOFF(t % ST_AGES));

#pragma unroll
        for (int kk = 0; kk < BK; kk += 8) {
            uint32_t a[4][4], b[8][2];
            const int c0 = kk + tig;
#pragma unroll
            for (int mt = 0; mt < 4; mt++) {
                int r0 = wm + mt * 16 + grp;
                a[mt][0] = as[r0 * SL + c0];
                a[mt][1] = as[(r0 + 8) * SL + c0];
                a[mt][2] = as[r0 * SL + c0 + 4];
                a[mt][3] = as[(r0 + 8) * SL + c0 + 4];
                if (RA) {
#pragma unroll
                    for (int q = 0; q < 4; q++)
                        a[mt][q] = __float_as_uint(to_tf32(__uint_as_float(a[mt][q])));
                }
            }
#pragma unroll
            for (int nt = 0; nt < 8; nt++) {
                int n0 = wn + nt * 8 + grp;
                b[nt][0] = bs[n0 * SL + c0];
                b[nt][1] = bs[n0 * SL + c0 + 4];
            }
#pragma unroll
            for (int mt = 0; mt < 4; mt++)
#pragma unroll
                for (int nt = 0; nt < 8; nt++) {
                    asm volatile(
                        "mma.sync.aligned.m16n8k8.row.col.f32.tf32.tf32.f32 "
                        "{%0,%1,%2,%3}, {%4,%5,%6,%7}, {%8,%9}, {%0,%1,%2,%3};"
                        : "+f"(acc[mt][nt][0]), "+f"(acc[mt][nt][1]),
                          "+f"(acc[mt][nt][2]), "+f"(acc[mt][nt][3])
                        : "r"(a[mt][0]), "r"(a[mt][1]), "r"(a[mt][2]), "r"(a[mt][3]),
                          "r"(b[nt][0]), "r"(b[nt][1]));
                }
        }
        __syncthreads();
    }
#undef LOAD_TILE

    if (cmode == 2 && bn == 256) {
        float myp[4][2];
#pragma unroll
        for (int mt = 0; mt < 4; mt++) { myp[mt][0] = 0.f; myp[mt][1] = 0.f; }
#pragma unroll
        for (int nt = 0; nt < 8; nt++)
#pragma unroll
            for (int e = 0; e < 4; e++) {
                int col = bn + wn + nt * 8 + tig * 2 + (e & 1);
                float wv = __ldg(w2 + (col - 256));
                float bv = __ldg(bias0 + col);
#pragma unroll
                for (int mt = 0; mt < 4; mt++) {
                    float v = fmaxf(acc[mt][nt][e] + bv, 0.f);
                    myp[mt][e >> 1] += v * wv;
                }
            }
#pragma unroll
        for (int mt = 0; mt < 4; mt++)
#pragma unroll
            for (int h = 0; h < 2; h++) {
                float v = myp[mt][h];
                v += __shfl_xor_sync(0xffffffffu, v, 1);
                v += __shfl_xor_sync(0xffffffffu, v, 2);
                myp[mt][h] = v;
            }
        if (tig == 0) {
            int wi = warp >> 1;
#pragma unroll
            for (int mt = 0; mt < 4; mt++)
#pragma unroll
                for (int h = 0; h < 2; h++)
                    spart[wi][wm + mt * 16 + grp + 8 * h] = myp[mt][h];
        }
        __syncthreads();
        if (tid < BM)
            stopP[bm + tid] = spart[0][tid] + spart[1][tid] + spart[2][tid] + spart[3][tid];
        return;
    }

#pragma unroll
    for (int nt = 0; nt < 8; nt++) {
#pragma unroll
        for (int e = 0; e < 4; e++) {
            int col = bn + wn + nt * 8 + tig * 2 + (e & 1);
            if (col >= N) continue;
            float bv = 0.f;
            if (bias0) bv += __ldg(bias0 + col);
            if (bias1) bv += __ldg(bias1 + col);
#pragma unroll
            for (int mt = 0; mt < 4; mt++) {
                int row = bm + wm + mt * 16 + grp + ((e >> 1) << 3);
                float v = acc[mt][nt][e] + bv;
                if (dorelu) v = fmaxf(v, 0.f);
                if (doround) v = to_tf32(v);
                if (cmode == 0)
                    C[(size_t)row * N + col] = v;
                else if (cmode == 1)
                    C[(size_t)(row >> 6) * (64 * (size_t)N) + (size_t)col * 64 + (row & 63)] = v;
                else
                    C[(size_t)row * 256 + col] = v;
            }
        }
    }
}

// ---------------- stop finalize ----------------
__global__ void stopfin_k(const float* __restrict__ b2, float* __restrict__ out) {
    int r = blockIdx.x * 256 + threadIdx.x;
    if (r < M_DEC) out[r] = g_StopP[r] + b2[0];
}

// ---------------- recurrent LSTM: 4 independent batch chains x 32 CTAs ----------------
__device__ __forceinline__ float sigmoidf_(float x) { return 1.f / (1.f + __expf(-x)); }

__device__ __forceinline__ void bar_wait(int tid, unsigned int tgt, unsigned int* barp) {
    if (tid == 0) {
        unsigned int v;
        do { asm volatile("ld.acquire.gpu.u32 %0, [%1];" : "=r"(v) : "l"(barp)); }
        while (v < tgt);
    }
    __syncthreads();
}
__device__ __forceinline__ void bar_arrive(int tid, unsigned int* barp) {
    __syncthreads();
    if (tid == 0)
        asm volatile("red.release.gpu.add.u32 [%0], %1;" :: "l"(barp), "r"(1u) : "memory");
}

#define SEQ_NB 128
#define SEQ_NT 256
#define CHAIN_CTAS 32
#define WPAD 258
#define LSTM_SMEM ((2 * 32 * WPAD + 8 * 32 * 16) * 4)

// DEC=0: encoder steps [0,LT); DEC=1: decoder steps [s0,s1e)
// chain = blk>>5 owns batches [chain*16, chain*16+16); cg = blk&31 owns h-cols [cg*8, cg*8+8)
template<int DEC>
__global__ void __launch_bounds__(SEQ_NT, 1) lstm_k(
    const float* __restrict__ Whh, const int* __restrict__ tlen, int s0, int s1e)
{
    extern __shared__ float sm[];
    float2* Ws2  = (float2*)sm;             // [32][WPAD]
    float*  part = sm + 2 * 32 * WPAD;      // [8][32][16]

    const int tid   = threadIdx.x;
    const int blk   = blockIdx.x;
    const int chain = blk >> 5;             // 0..3
    const int cg    = blk & 31;             // 0..31
    const int j0    = cg * 8;
    const int b0    = chain * 16;
    unsigned int* barp = &g_bar4[chain * 32];
    const int warp = tid >> 5, lane = tid & 31;
    const int rg   = lane >> 2;
    const int bpg  = lane & 3;
    const int kbeg = warp * 32;

    for (int idx = tid; idx < 32 * 256; idx += SEQ_NT) {
        int gl = idx >> 8, k = idx & 255;
        int g = gl >> 3, jj = gl & 7;
        float w = Whh[(g * 256 + j0 + jj) * 256 + k];
        Ws2[gl * WPAD + k] = make_float2(w, w);
    }

    const int ujj = tid >> 4, ubb = tid & 15;
    const int uj = j0 + ujj, ub = b0 + ubb;
    const bool upd = (tid < 128);
    float c_reg = 0.f;
    const int mylen = (DEC == 0 && upd) ? tlen[ub] : 0;
    if (DEC == 1 && upd && s0 > LT) c_reg = g_cbuf[uj * 64 + ub];
    __syncthreads();

    for (int s = s0; s < s1e; s++) {
        // prefetch x-part gate values BEFORE the barrier (h-independent)
        float gvx[4];
        if (upd) {
            if (DEC == 1) {
                int t = s - LT;
                if (t < 800) {
#pragma unroll
                    for (int g = 0; g < 4; g++)
                        gvx[g] = __ldcg(g_XdG + (size_t)t * ((size_t)G4 * NB_)
                                        + ((g * 256 + uj) << 6) + ub);
                } else {
#pragma unroll
                    for (int g = 0; g < 4; g++)
                        gvx[g] = __ldg(g_cvec + g * 256 + uj);
                }
            } else {
#pragma unroll
                for (int g = 0; g < 4; g++)
                    gvx[g] = __ldcg(g_XencG + (size_t)s * (G4 * NB_)
                                    + ((g * 256 + uj) << 6) + ub);
            }
        }

        bar_wait(tid, (unsigned int)(CHAIN_CTAS * s), barp);

        const int cur = s & 1, nxt = cur ^ 1;
        const float* hb = g_hbuf + cur * (D_H * NB_);

        unsigned long long acc[4][2];
#pragma unroll
        for (int i = 0; i < 4; i++) { acc[i][0] = 0ull; acc[i][1] = 0ull; }
#pragma unroll 8
        for (int k = kbeg; k < kbeg + 32; k++) {
            ulonglong2 hq = __ldcg((const ulonglong2*)(hb + k * 64 + b0 + bpg * 4));
#pragma unroll
            for (int i = 0; i < 4; i++) {
                unsigned long long w = *(const unsigned long long*)&Ws2[(rg * 4 + i) * WPAD + k];
                asm("fma.rn.f32x2 %0, %1, %2, %0;" : "+l"(acc[i][0]) : "l"(hq.x), "l"(w));
                asm("fma.rn.f32x2 %0, %1, %2, %0;" : "+l"(acc[i][1]) : "l"(hq.y), "l"(w));
            }
        }
#pragma unroll
        for (int i = 0; i < 4; i++) {
            *(float2*)&part[(warp * 32 + rg * 4 + i) * 16 + bpg * 4 + 0] = *(float2*)&acc[i][0];
            *(float2*)&part[(warp * 32 + rg * 4 + i) * 16 + bpg * 4 + 2] = *(float2*)&acc[i][1];
        }
        __syncthreads();

        if (upd) {
            float gv[4];
#pragma unroll
            for (int g = 0; g < 4; g++) {
                int gl = g * 8 + ujj;
                float v = gvx[g];
#pragma unroll
                for (int w = 0; w < 8; w++) v += part[(w * 32 + gl) * 16 + ubb];
                gv[g] = v;
            }
            if (DEC == 1 && s == LT)
                c_reg = __ldcg(hb + uj * 64 + ub);

            float iv = sigmoidf_(gv[0]);
            float fv = sigmoidf_(gv[1]);
            float gg = tanhf(gv[2]);
            float ov = sigmoidf_(gv[3]);
            float c2 = fv * c_reg + iv * gg;
            float h2 = ov * tanhf(c2);
            float hnew;
            if (DEC == 0) {
                bool m = (s < mylen);
                float hold = __ldcg(hb + uj * 64 + ub);
                c_reg = m ? c2 : c_reg;
                hnew  = m ? h2 : hold;
            } else {
                c_reg = c2;
                hnew  = h2;
                g_H[(size_t)(s - LT) * (NB_ * D_H) + ub * D_H + uj] = to_tf32(h2);
            }
            g_hbuf[nxt * (D_H * NB_) + uj * 64 + ub] = hnew;
        }
        bar_arrive(tid, barp);
    }
    if (DEC == 1 && upd) g_cbuf[uj * 64 + ub] = c_reg;
}

// ---------------- launch ----------------
extern "C" void kernel_launch(void* const* d_in, const int* in_sizes, int n_in,
                              void* d_out, int out_size) {
    const int*   token_pad     = (const int*)  d_in[0];
    const int*   token_lengths = (const int*)  d_in[1];
    const float* S_true        = (const float*)d_in[2];
    const float* emb           = (const float*)d_in[3];
    const float* enc_Wih       = (const float*)d_in[4];
    const float* enc_Whh       = (const float*)d_in[5];
    const float* enc_bih       = (const float*)d_in[6];
    const float* enc_bhh       = (const float*)d_in[7];
    const float* dec_Wih       = (const float*)d_in[8];
    const float* dec_Whh       = (const float*)d_in[9];
    const float* dec_bih       = (const float*)d_in[10];
    const float* dec_bhh       = (const float*)d_in[11];
    const float* pre_W         = (const float*)d_in[12];
    const float* pre_b         = (const float*)d_in[13];
    const float* post_W1       = (const float*)d_in[14];
    const float* post_b1       = (const float*)d_in[15];
    const float* post_W2       = (const float*)d_in[16];
    const float* post_b2       = (const float*)d_in[17];
    const float* stop_W1       = (const float*)d_in[18];
    const float* stop_b1       = (const float*)d_in[19];
    const float* stop_W2       = (const float*)d_in[20];
    const float* stop_b2       = (const float*)d_in[21];
    float* out = (float*)d_out;

    float *pTE, *pXencG, *pXd, *pXdG, *pH, *pHid, *pWr, *pStopP, *pBcat;
    cudaGetSymbolAddress((void**)&pTE,    g_TE);
    cudaGetSymbolAddress((void**)&pXencG, g_XencG);
    cudaGetSymbolAddress((void**)&pXd,    g_Xd);
    cudaGetSymbolAddress((void**)&pXdG,   g_XdG);
    cudaGetSymbolAddress((void**)&pH,     g_H);
    cudaGetSymbolAddress((void**)&pHid,   g_Hid);
    cudaGetSymbolAddress((void**)&pWr,    g_Wr);
    cudaGetSymbolAddress((void**)&pStopP, g_StopP);
    cudaGetSymbolAddress((void**)&pBcat,  g_bcat);

    static bool s_init = false;
    static cudaStream_t s1, s2;
    static cudaEvent_t evR, evD, evJ, evL[NSEG];
    if (!s_init) {
        s_init = true;
        cudaStreamCreateWithFlags(&s1, cudaStreamNonBlocking);
        cudaStreamCreateWithFlags(&s2, cudaStreamNonBlocking);
        cudaEventCreateWithFlags(&evR, cudaEventDisableTiming);
        cudaEventCreateWithFlags(&evD, cudaEventDisableTiming);
        cudaEventCreateWithFlags(&evJ, cudaEventDisableTiming);
        for (int i = 0; i < NSEG; i++) cudaEventCreateWithFlags(&evL[i], cudaEventDisableTiming);
        cudaFuncSetAttribute(gemm_tc<0>, cudaFuncAttributeMaxDynamicSharedMemorySize, GEMM_SMEM);
        cudaFuncSetAttribute(gemm_tc<1>, cudaFuncAttributeMaxDynamicSharedMemorySize, GEMM_SMEM);
        cudaFuncSetAttribute(lstm_k<0>,  cudaFuncAttributeMaxDynamicSharedMemorySize, LSTM_SMEM);
        cudaFuncSetAttribute(lstm_k<1>,  cudaFuncAttributeMaxDynamicSharedMemorySize, LSTM_SMEM);
    }

    // ---- stream 0: prep ----
    prep_k<<<(P_W2 + 255) / 256, 256>>>(enc_Wih, dec_Wih, pre_W, post_W1, stop_W1, post_W2,
                                        post_b1, stop_b1);
    gather_emb<<<M_ENC, 256>>>(token_pad, emb, pTE);
    cudaEventRecord(evR, 0);
    gemm_tc<0><<<dim3(M_ENC/128, G4/256), 256, GEMM_SMEM>>>(pTE, 256, 0, M_ENC, 256,
        pWr + W_ENC, 256, enc_bih, enc_bhh, pXencG, M_ENC, G4, 256, 1, 0, 0, nullptr, nullptr);
    lstm_k<0><<<SEQ_NB, SEQ_NT, LSTM_SMEM>>>(enc_Whh, token_lengths, 0, LT);

    // ---- s1: pre-net + dec-gate + cvec, overlapping the encoder ----
    cudaStreamWaitEvent(s1, evR, 0);
    gemm_tc<1><<<dim3(M_VAL/128, 1), 256, GEMM_SMEM, s1>>>(S_true, D_S, 64, M_VAL, D_S,
        pWr + W_PRE, KP_S, pre_b, nullptr, pXd, M_VAL, D_H, KP_S, 0, 0, 1, nullptr, nullptr);
    gemm_tc<0><<<dim3(M_VAL/128, G4/256), 256, GEMM_SMEM, s1>>>(pXd, 256, 0, M_VAL, 256,
        pWr + W_DEC, 256, dec_bih, dec_bhh, pXdG, M_VAL, G4, 256, 1, 0, 0, nullptr, nullptr);
    cvec_k<<<G4/8, 256, 0, s1>>>(pre_b, dec_bih, dec_bhh);
    cudaEventRecord(evD, s1);

    // ---- stream 0: decoder recurrence in segments ----
    cudaStreamWaitEvent(0, evD, 0);
    for (int i = 0; i < NSEG; i++) {
        lstm_k<1><<<SEQ_NB, SEQ_NT, LSTM_SMEM>>>(dec_Whh, token_lengths,
                                                 LT + i * SEG_STEPS, LT + (i + 1) * SEG_STEPS);
        cudaEventRecord(evL[i], 0);
    }

    // ---- s2: per-segment post-net chunks overlap the decoder recurrence ----
    for (int i = 0; i < NSEG; i++) {
        cudaStreamWaitEvent(s2, evL[i], 0);
        const float* Hc  = pH   + (size_t)SEG_ROWS * i * 256;
        float*       Hic = pHid + (size_t)SEG_ROWS * i * 256;
        gemm_tc<0><<<dim3(SEG_ROWS/128, 2), 256, GEMM_SMEM, s2>>>(Hc, 256, 0, SEG_ROWS, 256,
            pWr + W_P1S, 256, pBcat, nullptr, Hic, SEG_ROWS, 512, 256, 2, 1, 1,
            stop_W2, pStopP + (size_t)SEG_ROWS * i);
        gemm_tc<0><<<dim3(SEG_ROWS/128, 3), 256, GEMM_SMEM, s2>>>(Hic, 256, 0, SEG_ROWS, 256,
            pWr + W_POST2, 256, post_b2, nullptr, out + (size_t)SEG_ROWS * i * D_S,
            SEG_ROWS, D_S, 256, 0, 0, 0, nullptr, nullptr);
    }
    stopfin_k<<<(M_DEC+255)/256, 256, 0, s2>>>(stop_b2, out + STOP_OFF);
    cudaEventRecord(evJ, s2);

    cudaStreamWaitEvent(0, evJ, 0);
}